// round 1
// baseline (speedup 1.0000x reference)
#include <cuda_runtime.h>

#define SB 2
#define SX 160
#define SY 192
#define SZ 160
#define WIN 21
#define HALF 10
#define NF 9830400            // SB*SX*SY*SZ
#define XSEG 2
#define XLEN (SX / XSEG)      // 80
#define NPART (SB * SY * XSEG) // 768

// Scratch: 5 channels (I, J, I2, J2, IJ), two ping-pong volumes.
__device__ float g_s1[5ull * NF];
__device__ float g_s2[5ull * NF];
__device__ double g_part[NPART];

// ---------------------------------------------------------------------------
// Pass A: form the 5 product channels and box-filter along Z (contiguous axis).
// One block = one z-line (160 threads, thread == z). smem tap window.
// All global loads/stores coalesced along z.
// ---------------------------------------------------------------------------
__global__ __launch_bounds__(SZ) void passA(const float* __restrict__ I,
                                            const float* __restrict__ J) {
    __shared__ float2 s[SZ];
    int bid = blockIdx.x;          // over SB*SX*SY lines
    int y = bid % SY;
    int t = bid / SY;
    int x = t % SX;
    int b = t / SX;
    int z = threadIdx.x;

    size_t base = (((size_t)(b * SX + x)) * SY + y) * SZ;
    float iv = I[base + z];
    float jv = J[base + z];
    s[z] = make_float2(iv, jv);
    __syncthreads();

    float sI = 0.f, sJ = 0.f, sI2 = 0.f, sJ2 = 0.f, sIJ = 0.f;
#pragma unroll
    for (int k = -HALF; k <= HALF; k++) {
        int zz = z + k;
        if (zz >= 0 && zz < SZ) {
            float2 v = s[zz];
            sI  += v.x;
            sJ  += v.y;
            sI2 += v.x * v.x;
            sJ2 += v.y * v.y;
            sIJ += v.x * v.y;
        }
    }
    size_t o = base + z;
    g_s1[0ull * NF + o] = sI;
    g_s1[1ull * NF + o] = sJ;
    g_s1[2ull * NF + o] = sI2;
    g_s1[3ull * NF + o] = sJ2;
    g_s1[4ull * NF + o] = sIJ;
}

// ---------------------------------------------------------------------------
// Pass B: box-filter along Y. Thread == z (coalesced), running sliding sum.
// The subtracted element is re-loaded (21 rows back -> L1 hit).
// Grid: 5 channels * SB * SX blocks.
// ---------------------------------------------------------------------------
__global__ __launch_bounds__(SZ) void passB() {
    int bid = blockIdx.x;
    int x = bid % SX;
    int t = bid / SX;
    int b = t % SB;
    int c = t / SB;
    int z = threadIdx.x;

    const float* __restrict__ in = g_s1 + (size_t)c * NF;
    float* __restrict__ out = g_s2 + (size_t)c * NF;
    size_t base = (((size_t)(b * SX + x)) * SY) * SZ + z;

    float sum = 0.f;
#pragma unroll
    for (int y = 0; y <= HALF; y++)
        sum += in[base + (size_t)y * SZ];

    for (int y = 0; y < SY; y++) {
        out[base + (size_t)y * SZ] = sum;
        int ya = y + HALF + 1;
        int yr = y - HALF;
        if (ya < SY) sum += in[base + (size_t)ya * SZ];
        if (yr >= 0) sum -= in[base + (size_t)yr * SZ];
    }
}

// ---------------------------------------------------------------------------
// Pass C: box-filter along X with 5 concurrent running sums, compute cc
// per voxel, accumulate, block-reduce to a per-block partial (deterministic).
// Grid: SB * SY * XSEG blocks, thread == z.
// ---------------------------------------------------------------------------
__global__ __launch_bounds__(SZ) void passC() {
    int bid = blockIdx.x;
    int seg = bid % XSEG;
    int t = bid / XSEG;
    int y = t % SY;
    int b = t / SY;
    int z = threadIdx.x;

    const int x0 = seg * XLEN;
    const size_t strideX = (size_t)SY * SZ;
    size_t base = ((size_t)b * SX) * strideX + (size_t)y * SZ + z;

    float s0 = 0.f, s1 = 0.f, s2 = 0.f, s3 = 0.f, s4 = 0.f;
#pragma unroll
    for (int xx = x0 - HALF; xx <= x0 + HALF; xx++) {
        if (xx >= 0 && xx < SX) {
            size_t o = base + (size_t)xx * strideX;
            s0 += g_s2[0ull * NF + o];
            s1 += g_s2[1ull * NF + o];
            s2 += g_s2[2ull * NF + o];
            s3 += g_s2[3ull * NF + o];
            s4 += g_s2[4ull * NF + o];
        }
    }

    const float inv_n = 1.0f / (float)(WIN * WIN * WIN);
    float acc = 0.f;
    for (int x = x0; x < x0 + XLEN; x++) {
        float cross = s4 - s0 * s1 * inv_n;
        float Ivar  = s2 - s0 * s0 * inv_n;
        float Jvar  = s3 - s1 * s1 * inv_n;
        float cc = (cross * cross) / (Ivar * Jvar + 1e-5f);
        acc += cc;

        int xa = x + HALF + 1;
        int xr = x - HALF;
        if (xa < SX) {
            size_t o = base + (size_t)xa * strideX;
            s0 += g_s2[0ull * NF + o];
            s1 += g_s2[1ull * NF + o];
            s2 += g_s2[2ull * NF + o];
            s3 += g_s2[3ull * NF + o];
            s4 += g_s2[4ull * NF + o];
        }
        if (xr >= 0) {
            size_t o = base + (size_t)xr * strideX;
            s0 -= g_s2[0ull * NF + o];
            s1 -= g_s2[1ull * NF + o];
            s2 -= g_s2[2ull * NF + o];
            s3 -= g_s2[3ull * NF + o];
            s4 -= g_s2[4ull * NF + o];
        }
    }

    // Block reduction (160 threads = 5 warps), deterministic.
    __shared__ float wsum[SZ / 32];
    float v = acc;
#pragma unroll
    for (int off = 16; off; off >>= 1)
        v += __shfl_down_sync(0xffffffffu, v, off);
    if ((threadIdx.x & 31) == 0) wsum[threadIdx.x >> 5] = v;
    __syncthreads();
    if (threadIdx.x == 0) {
        double tot = 0.0;
#pragma unroll
        for (int w = 0; w < SZ / 32; w++) tot += (double)wsum[w];
        g_part[bid] = tot;
    }
}

// ---------------------------------------------------------------------------
// Final: reduce partials, out = 1 - mean(cc)
// ---------------------------------------------------------------------------
__global__ void finalK(float* __restrict__ out) {
    __shared__ double sh[256];
    double v = 0.0;
    for (int i = threadIdx.x; i < NPART; i += 256)
        v += g_part[i];
    sh[threadIdx.x] = v;
    __syncthreads();
    for (int s = 128; s; s >>= 1) {
        if (threadIdx.x < s) sh[threadIdx.x] += sh[threadIdx.x + s];
        __syncthreads();
    }
    if (threadIdx.x == 0)
        out[0] = (float)(1.0 - sh[0] / (double)NF);
}

extern "C" void kernel_launch(void* const* d_in, const int* in_sizes, int n_in,
                              void* d_out, int out_size) {
    const float* I = (const float*)d_in[0];
    const float* J = (const float*)d_in[1];
    float* out = (float*)d_out;

    passA<<<SB * SX * SY, SZ>>>(I, J);
    passB<<<5 * SB * SX, SZ>>>();
    passC<<<SB * SY * XSEG, SZ>>>();
    finalK<<<1, 256>>>(out);
}

// round 2
// speedup vs baseline: 1.3720x; 1.3720x over previous
#include <cuda_runtime.h>
#include <cuda_fp16.h>

#define SB 2
#define SX 160
#define SY 192
#define SZ 160
#define WIN 21
#define HALF 10
#define NF 9830400ull          // SB*SX*SY*SZ
#define YSEG 2
#define YL (SY / YSEG)         // 96
#define XSEG 2
#define XLEN (SX / XSEG)       // 80
#define NPART (SB * SY * XSEG) // 768

// Intermediate: 5 channels (I, J, I2, J2, IJ) after z+y box filtering, fp16.
__device__ __half g_h[5 * NF];
__device__ double g_part[NPART];

// ---------------------------------------------------------------------------
// Fused pass A+B: form products, box-filter along Z (21 smem taps on the
// contiguous axis), then box-filter along Y with a per-thread running sum and
// a 21-line fp16 ring buffer. One block = (batch, x, y-segment); thread == z.
// The half-rounded value is both added to the running sum and stored in the
// ring, so the later subtraction cancels exactly (no drift).
// ---------------------------------------------------------------------------
__global__ __launch_bounds__(SZ) void passAB(const float* __restrict__ I,
                                             const float* __restrict__ J) {
    __shared__ float2 line[2][SZ + 2 * HALF];   // zero-padded, double buffered
    __shared__ __half ring[WIN][5][SZ];         // per-thread-z slots only

    const int z = threadIdx.x;
    int bid = blockIdx.x;
    const int seg = bid % YSEG;
    int t = bid / YSEG;
    const int x = t % SX;
    const int b = t / SX;

    // zero the halo pads once
    if (z < HALF) {
        float2 zero = make_float2(0.f, 0.f);
        line[0][z] = zero;               line[1][z] = zero;
        line[0][SZ + HALF + z] = zero;   line[1][SZ + HALF + z] = zero;
    }

    const int y0 = seg * YL;
    const int y1 = y0 + YL;
    const int ystart = (y0 - HALF > 0) ? (y0 - HALF) : 0;

    const size_t planeBase = ((size_t)(b * SX + x)) * SY * SZ;

    float c0 = 0.f, c1 = 0.f, c2 = 0.f, c3 = 0.f, c4 = 0.f;
    int slot = 0, buf = 0;

    __syncthreads();   // pads visible

    for (int y = ystart; y < y1 + HALF; ++y) {
        // stage the input line (coalesced along z)
        if (y < SY) {
            size_t o = planeBase + (size_t)y * SZ + z;
            line[buf][HALF + z] = make_float2(I[o], J[o]);
        }
        // read the value leaving the y-window BEFORE overwriting the slot
        float s0 = 0.f, s1 = 0.f, s2 = 0.f, s3 = 0.f, s4 = 0.f;
        if (y - WIN >= ystart) {
            s0 = __half2float(ring[slot][0][z]);
            s1 = __half2float(ring[slot][1][z]);
            s2 = __half2float(ring[slot][2][z]);
            s3 = __half2float(ring[slot][3][z]);
            s4 = __half2float(ring[slot][4][z]);
        }
        __syncthreads();

        float f0 = 0.f, f1 = 0.f, f2 = 0.f, f3 = 0.f, f4 = 0.f;
        if (y < SY) {
            // 21-tap z filter of the 5 product channels
#pragma unroll
            for (int k = 0; k < WIN; ++k) {
                float2 v = line[buf][z + k];
                f0 += v.x;
                f1 += v.y;
                f2 += v.x * v.x;
                f3 += v.y * v.y;
                f4 += v.x * v.y;
            }
            __half h0 = __float2half(f0), h1 = __float2half(f1),
                   h2 = __float2half(f2), h3 = __float2half(f3),
                   h4 = __float2half(f4);
            ring[slot][0][z] = h0;
            ring[slot][1][z] = h1;
            ring[slot][2][z] = h2;
            ring[slot][3][z] = h3;
            ring[slot][4][z] = h4;
            // use the rounded values so add/sub cancels exactly
            f0 = __half2float(h0); f1 = __half2float(h1);
            f2 = __half2float(h2); f3 = __half2float(h3);
            f4 = __half2float(h4);
        }
        c0 += f0 - s0; c1 += f1 - s1; c2 += f2 - s2;
        c3 += f3 - s3; c4 += f4 - s4;

        const int yo = y - HALF;
        if (yo >= y0) {
            size_t o = planeBase + (size_t)yo * SZ + z;
            g_h[0 * NF + o] = __float2half(c0);
            g_h[1 * NF + o] = __float2half(c1);
            g_h[2 * NF + o] = __float2half(c2);
            g_h[3 * NF + o] = __float2half(c3);
            g_h[4 * NF + o] = __float2half(c4);
        }
        slot = (slot + 1 == WIN) ? 0 : slot + 1;
        buf ^= 1;
    }
}

// ---------------------------------------------------------------------------
// Pass C: box-filter along X with 5 running sums (fp16 loads, fp32 accum),
// compute cc per voxel, block-reduce deterministically to a partial.
// The 21-x add/sub window stays L2-resident (26 MB live << 126 MB L2).
// ---------------------------------------------------------------------------
__global__ __launch_bounds__(SZ) void passC() {
    int bid = blockIdx.x;
    const int seg = bid % XSEG;
    int t = bid / XSEG;
    const int y = t % SY;
    const int b = t / SY;
    const int z = threadIdx.x;

    const int x0 = seg * XLEN;
    const size_t strideX = (size_t)SY * SZ;
    const size_t base = ((size_t)b * SX) * strideX + (size_t)y * SZ + z;

    float s0 = 0.f, s1 = 0.f, s2 = 0.f, s3 = 0.f, s4 = 0.f;
#pragma unroll
    for (int xx = x0 - HALF; xx <= x0 + HALF; ++xx) {
        if (xx >= 0 && xx < SX) {
            size_t o = base + (size_t)xx * strideX;
            s0 += __half2float(g_h[0 * NF + o]);
            s1 += __half2float(g_h[1 * NF + o]);
            s2 += __half2float(g_h[2 * NF + o]);
            s3 += __half2float(g_h[3 * NF + o]);
            s4 += __half2float(g_h[4 * NF + o]);
        }
    }

    const float inv_n = 1.0f / (float)(WIN * WIN * WIN);
    float acc = 0.f;
    for (int x = x0; x < x0 + XLEN; ++x) {
        float cross = s4 - s0 * s1 * inv_n;
        float Ivar  = s2 - s0 * s0 * inv_n;
        float Jvar  = s3 - s1 * s1 * inv_n;
        acc += (cross * cross) / (Ivar * Jvar + 1e-5f);

        const int xa = x + HALF + 1;
        const int xr = x - HALF;
        if (xa < SX) {
            size_t o = base + (size_t)xa * strideX;
            s0 += __half2float(g_h[0 * NF + o]);
            s1 += __half2float(g_h[1 * NF + o]);
            s2 += __half2float(g_h[2 * NF + o]);
            s3 += __half2float(g_h[3 * NF + o]);
            s4 += __half2float(g_h[4 * NF + o]);
        }
        if (xr >= 0) {
            size_t o = base + (size_t)xr * strideX;
            s0 -= __half2float(g_h[0 * NF + o]);
            s1 -= __half2float(g_h[1 * NF + o]);
            s2 -= __half2float(g_h[2 * NF + o]);
            s3 -= __half2float(g_h[3 * NF + o]);
            s4 -= __half2float(g_h[4 * NF + o]);
        }
    }

    // deterministic block reduction (160 threads = 5 warps)
    __shared__ float wsum[SZ / 32];
    float v = acc;
#pragma unroll
    for (int off = 16; off; off >>= 1)
        v += __shfl_down_sync(0xffffffffu, v, off);
    if ((threadIdx.x & 31) == 0) wsum[threadIdx.x >> 5] = v;
    __syncthreads();
    if (threadIdx.x == 0) {
        double tot = 0.0;
#pragma unroll
        for (int w = 0; w < SZ / 32; w++) tot += (double)wsum[w];
        g_part[bid] = tot;
    }
}

// ---------------------------------------------------------------------------
// Final: reduce partials, out = 1 - mean(cc)
// ---------------------------------------------------------------------------
__global__ void finalK(float* __restrict__ out) {
    __shared__ double sh[256];
    double v = 0.0;
    for (int i = threadIdx.x; i < NPART; i += 256)
        v += g_part[i];
    sh[threadIdx.x] = v;
    __syncthreads();
    for (int s = 128; s; s >>= 1) {
        if (threadIdx.x < s) sh[threadIdx.x] += sh[threadIdx.x + s];
        __syncthreads();
    }
    if (threadIdx.x == 0)
        out[0] = (float)(1.0 - sh[0] / (double)(5ull * NF / 5ull));
}

extern "C" void kernel_launch(void* const* d_in, const int* in_sizes, int n_in,
                              void* d_out, int out_size) {
    const float* I = (const float*)d_in[0];
    const float* J = (const float*)d_in[1];
    float* out = (float*)d_out;

    passAB<<<SB * SX * YSEG, SZ>>>(I, J);
    passC<<<SB * SY * XSEG, SZ>>>();
    finalK<<<1, 256>>>(out);
}

// round 3
// speedup vs baseline: 1.7580x; 1.2813x over previous
#include <cuda_runtime.h>
#include <cuda_fp16.h>

#define SB 2
#define SX 160
#define SY 192
#define SZ 160
#define WIN 21
#define HALF 10
#define NF 9830400ull          // SB*SX*SY*SZ
#define YSEG 4
#define YL (SY / YSEG)         // 48
#define XSEG 4
#define XLEN (SX / XSEG)       // 40
#define NPART (SB * SY * XSEG) // 1536

// Packed fp16 intermediate: (I,J,I2,J2) in one 8-byte quad + IJ separate.
struct __align__(8) H4 { __half2 a, b; };

__device__ H4 g_q[NF];
__device__ __half g_e[NF];
__device__ double g_part[NPART];

// ---------------------------------------------------------------------------
// Fused pass A+B: products + z box filter (21 smem taps on fp16-staged lines)
// + y box filter (per-thread running sum, 21-line packed fp16 ring).
// 2 y-lines per barrier, double-buffered staging. Thread == z.
// Rounded-half values are both added and later subtracted -> exact cancel.
// ---------------------------------------------------------------------------
__global__ __launch_bounds__(SZ) void passAB(const float* __restrict__ I,
                                             const float* __restrict__ J) {
    __shared__ __half2 line[2][2][SZ + 2 * HALF]; // [buf][line-in-pair][z]
    __shared__ H4 ringQ[WIN][SZ];
    __shared__ __half ringE[WIN][SZ];

    const int z = threadIdx.x;
    int bid = blockIdx.x;
    const int seg = bid % YSEG;
    int t = bid / YSEG;
    const int x = t % SX;
    const int b = t / SX;

    // zero halo pads once
    if (z < HALF) {
        __half2 zero = __floats2half2_rn(0.f, 0.f);
#pragma unroll
        for (int bf = 0; bf < 2; bf++)
#pragma unroll
            for (int l = 0; l < 2; l++) {
                line[bf][l][z] = zero;
                line[bf][l][SZ + HALF + z] = zero;
            }
    }

    const int y0 = seg * YL;
    const int y1 = y0 + YL;
    const int ystart = (y0 - HALF > 0) ? (y0 - HALF) : 0; // always even
    const size_t planeBase = ((size_t)(b * SX + x)) * SY * SZ;

    float c0 = 0.f, c1 = 0.f, c2 = 0.f, c3 = 0.f, c4 = 0.f;
    int slot = 0, buf = 0;

    __syncthreads();

    for (int y = ystart; y < y1 + HALF; y += 2) {
        // stage two lines (coalesced along z); zeros past the volume
#pragma unroll
        for (int l = 0; l < 2; l++) {
            int yy = y + l;
            __half2 v = __floats2half2_rn(0.f, 0.f);
            if (yy < SY) {
                size_t o = planeBase + (size_t)yy * SZ + z;
                v = __floats2half2_rn(I[o], J[o]);
            }
            line[buf][l][HALF + z] = v;
        }
        __syncthreads();

#pragma unroll
        for (int l = 0; l < 2; l++) {
            const int ycur = y + l;
            // 21-tap z filter of the 5 product channels
            float f0 = 0.f, f1 = 0.f, f2 = 0.f, f3 = 0.f, f4 = 0.f;
#pragma unroll
            for (int k = 0; k < WIN; k++) {
                float2 v = __half22float2(line[buf][l][z + k]);
                f0 += v.x;
                f1 += v.y;
                f2 = fmaf(v.x, v.x, f2);
                f3 = fmaf(v.y, v.y, f3);
                f4 = fmaf(v.x, v.y, f4);
            }
            H4 h;
            h.a = __floats2half2_rn(f0, f1);
            h.b = __floats2half2_rn(f2, f3);
            __half he = __float2half(f4);

            // subtract the line leaving the y window (read before overwrite)
            if (ycur - WIN >= ystart) {
                H4 o = ringQ[slot][z];
                float2 oa = __half22float2(o.a);
                float2 ob = __half22float2(o.b);
                c0 -= oa.x; c1 -= oa.y; c2 -= ob.x; c3 -= ob.y;
                c4 -= __half2float(ringE[slot][z]);
            }
            ringQ[slot][z] = h;
            ringE[slot][z] = he;
            float2 ra = __half22float2(h.a);
            float2 rb = __half22float2(h.b);
            c0 += ra.x; c1 += ra.y; c2 += rb.x; c3 += rb.y;
            c4 += __half2float(he);

            const int yo = ycur - HALF;
            if (yo >= y0) {
                size_t o = planeBase + (size_t)yo * SZ + z;
                H4 w;
                w.a = __floats2half2_rn(c0, c1);
                w.b = __floats2half2_rn(c2, c3);
                g_q[o] = w;
                g_e[o] = __float2half(c4);
            }
            slot = (slot + 1 == WIN) ? 0 : slot + 1;
        }
        buf ^= 1;
    }
}

// ---------------------------------------------------------------------------
// Pass C: x box filter with 5 running sums (packed fp16 loads, fp32 accum),
// cc per voxel, deterministic block reduction. Thread == z.
// ---------------------------------------------------------------------------
__global__ __launch_bounds__(SZ) void passC() {
    int bid = blockIdx.x;
    const int seg = bid % XSEG;
    int t = bid / XSEG;
    const int y = t % SY;
    const int b = t / SY;
    const int z = threadIdx.x;

    const int x0 = seg * XLEN;
    const size_t strideX = (size_t)SY * SZ;
    const size_t base = ((size_t)b * SX) * strideX + (size_t)y * SZ + z;

    float s0 = 0.f, s1 = 0.f, s2 = 0.f, s3 = 0.f, s4 = 0.f;
#pragma unroll
    for (int xx = x0 - HALF; xx <= x0 + HALF; ++xx) {
        if (xx >= 0 && xx < SX) {
            size_t o = base + (size_t)xx * strideX;
            H4 h = g_q[o];
            float2 a = __half22float2(h.a);
            float2 c = __half22float2(h.b);
            s0 += a.x; s1 += a.y; s2 += c.x; s3 += c.y;
            s4 += __half2float(g_e[o]);
        }
    }

    const float inv_n = 1.0f / (float)(WIN * WIN * WIN);
    float acc = 0.f;
    for (int x = x0; x < x0 + XLEN; ++x) {
        float cross = s4 - s0 * s1 * inv_n;
        float Ivar  = s2 - s0 * s0 * inv_n;
        float Jvar  = s3 - s1 * s1 * inv_n;
        acc += (cross * cross) / (Ivar * Jvar + 1e-5f);

        const int xa = x + HALF + 1;
        const int xr = x - HALF;
        if (xa < SX) {
            size_t o = base + (size_t)xa * strideX;
            H4 h = g_q[o];
            float2 a = __half22float2(h.a);
            float2 c = __half22float2(h.b);
            s0 += a.x; s1 += a.y; s2 += c.x; s3 += c.y;
            s4 += __half2float(g_e[o]);
        }
        if (xr >= 0) {
            size_t o = base + (size_t)xr * strideX;
            H4 h = g_q[o];
            float2 a = __half22float2(h.a);
            float2 c = __half22float2(h.b);
            s0 -= a.x; s1 -= a.y; s2 -= c.x; s3 -= c.y;
            s4 -= __half2float(g_e[o]);
        }
    }

    // deterministic block reduction (160 threads = 5 warps)
    __shared__ float wsum[SZ / 32];
    float v = acc;
#pragma unroll
    for (int off = 16; off; off >>= 1)
        v += __shfl_down_sync(0xffffffffu, v, off);
    if ((threadIdx.x & 31) == 0) wsum[threadIdx.x >> 5] = v;
    __syncthreads();
    if (threadIdx.x == 0) {
        double tot = 0.0;
#pragma unroll
        for (int w = 0; w < SZ / 32; w++) tot += (double)wsum[w];
        g_part[bid] = tot;
    }
}

// ---------------------------------------------------------------------------
// Final: reduce partials, out = 1 - mean(cc)
// ---------------------------------------------------------------------------
__global__ void finalK(float* __restrict__ out) {
    __shared__ double sh[256];
    double v = 0.0;
    for (int i = threadIdx.x; i < NPART; i += 256)
        v += g_part[i];
    sh[threadIdx.x] = v;
    __syncthreads();
    for (int s = 128; s; s >>= 1) {
        if (threadIdx.x < s) sh[threadIdx.x] += sh[threadIdx.x + s];
        __syncthreads();
    }
    if (threadIdx.x == 0)
        out[0] = (float)(1.0 - sh[0] / (double)NF);
}

extern "C" void kernel_launch(void* const* d_in, const int* in_sizes, int n_in,
                              void* d_out, int out_size) {
    const float* I = (const float*)d_in[0];
    const float* J = (const float*)d_in[1];
    float* out = (float*)d_out;

    passAB<<<SB * SX * YSEG, SZ>>>(I, J);
    passC<<<SB * SY * XSEG, SZ>>>();
    finalK<<<1, 256>>>(out);
}

// round 4
// speedup vs baseline: 1.8375x; 1.0453x over previous
#include <cuda_runtime.h>
#include <cuda_fp16.h>

#define SB 2
#define SX 160
#define SY 192
#define SZ 160
#define WIN 21
#define HALF 10
#define NF 9830400ull          // SB*SX*SY*SZ
#define YSEG 4
#define YL (SY / YSEG)         // 48
#define XSEG 2
#define XLEN (SX / XSEG)       // 80
#define NPART (SB * SY * XSEG) // 768
#define LPAD (SZ + 2 * HALF)   // 180
#define S1N (SZ + 18)          // stage1 index range [-9, SZ+9), offset +9

// Packed fp16 intermediate: (I,J,I2,J2) in one 8-byte quad + IJ separate.
struct __align__(8) H4 { __half2 a, b; };

__device__ H4 g_q[NF];
__device__ __half g_e[NF];
__device__ double g_part[NPART];

// ---------------------------------------------------------------------------
// Fused pass A+B. z-filter via hierarchical taps: stage1 = 3-tap (HADD2),
// stage2 = 7-tap stride-3 (HADD2)  ->  10 taps instead of 21, all packed fp16.
// y-filter: per-thread fp32 running sum with a 21-line packed fp16 ring
// (ring stores exactly the value added -> later subtraction cancels exactly).
// Thread == z. 2 lines per barrier pair.
// ---------------------------------------------------------------------------
__global__ __launch_bounds__(SZ) void passAB(const float* __restrict__ I,
                                             const float* __restrict__ J) {
    __shared__ __half2 lA[2][LPAD];   // (I, J)
    __shared__ __half2 lB[2][LPAD];   // (I2, J2)
    __shared__ __half  lC[2][LPAD];   // IJ
    __shared__ __half2 s1A[2][S1N];   // 3-tap partial sums
    __shared__ __half2 s1B[2][S1N];
    __shared__ __half  s1C[2][S1N];
    __shared__ H4 ringQ[WIN][SZ];
    __shared__ __half ringE[WIN][SZ];

    const int z = threadIdx.x;
    int bid = blockIdx.x;
    const int seg = bid % YSEG;
    int t = bid / YSEG;
    const int x = t % SX;
    const int b = t / SX;

    // zero the static z-halo pads once
    if (z < HALF) {
        const __half2 z2 = __floats2half2_rn(0.f, 0.f);
        const __half zh = __float2half(0.f);
#pragma unroll
        for (int l = 0; l < 2; l++) {
            lA[l][z] = z2; lA[l][SZ + HALF + z] = z2;
            lB[l][z] = z2; lB[l][SZ + HALF + z] = z2;
            lC[l][z] = zh; lC[l][SZ + HALF + z] = zh;
        }
    }

    const int y0 = seg * YL;
    const int y1 = y0 + YL;
    const int ystart = (y0 - HALF > 0) ? (y0 - HALF) : 0;  // even
    const size_t planeBase = ((size_t)(b * SX + x)) * SY * SZ;

    float c0 = 0.f, c1 = 0.f, c2 = 0.f, c3 = 0.f, c4 = 0.f;
    int slot = 0;

    __syncthreads();

    for (int y = ystart; y < y1 + HALF; y += 2) {
        // ---- phase 0: stage two lines + products (coalesced along z) ----
#pragma unroll
        for (int l = 0; l < 2; l++) {
            const int yy = y + l;
            float iv = 0.f, jv = 0.f;
            if (yy < SY) {
                size_t o = planeBase + (size_t)yy * SZ + z;
                iv = I[o]; jv = J[o];
            }
            __half2 v = __floats2half2_rn(iv, jv);
            lA[l][HALF + z] = v;
            lB[l][HALF + z] = __hmul2(v, v);
            lC[l][HALF + z] = __float2half(iv * jv);
        }
        __syncthreads();

        // ---- phase 1: 3-tap stage over [-9, SZ+9) (some threads do 2) ----
#pragma unroll
        for (int l = 0; l < 2; l++) {
            {
                const int i = z;  // lX physical idx = i, i+1, i+2
                s1A[l][i] = __hadd2(__hadd2(lA[l][i], lA[l][i + 1]), lA[l][i + 2]);
                s1B[l][i] = __hadd2(__hadd2(lB[l][i], lB[l][i + 1]), lB[l][i + 2]);
                s1C[l][i] = __hadd(__hadd(lC[l][i], lC[l][i + 1]), lC[l][i + 2]);
            }
            if (z < S1N - SZ) {
                const int i = SZ + z;
                s1A[l][i] = __hadd2(__hadd2(lA[l][i], lA[l][i + 1]), lA[l][i + 2]);
                s1B[l][i] = __hadd2(__hadd2(lB[l][i], lB[l][i + 1]), lB[l][i + 2]);
                s1C[l][i] = __hadd(__hadd(lC[l][i], lC[l][i + 1]), lC[l][i + 2]);
            }
        }
        __syncthreads();

        // ---- phase 2: 7-tap stride-3 stage + y running sum + output ----
#pragma unroll
        for (int l = 0; l < 2; l++) {
            const int ycur = y + l;
            // s1 physical indices z .. z+18 step 3
            __half2 a = s1A[l][z];
            __half2 bq = s1B[l][z];
            __half e = s1C[l][z];
#pragma unroll
            for (int j = 3; j <= 18; j += 3) {
                a = __hadd2(a, s1A[l][z + j]);
                bq = __hadd2(bq, s1B[l][z + j]);
                e = __hadd(e, s1C[l][z + j]);
            }
            H4 h; h.a = a; h.b = bq;

            if (ycur - WIN >= ystart) {
                H4 o = ringQ[slot][z];
                float2 oa = __half22float2(o.a);
                float2 ob = __half22float2(o.b);
                c0 -= oa.x; c1 -= oa.y; c2 -= ob.x; c3 -= ob.y;
                c4 -= __half2float(ringE[slot][z]);
            }
            ringQ[slot][z] = h;
            ringE[slot][z] = e;
            float2 ra = __half22float2(a);
            float2 rb = __half22float2(bq);
            c0 += ra.x; c1 += ra.y; c2 += rb.x; c3 += rb.y;
            c4 += __half2float(e);

            const int yo = ycur - HALF;
            if (yo >= y0) {
                size_t o = planeBase + (size_t)yo * SZ + z;
                H4 w;
                w.a = __floats2half2_rn(c0, c1);
                w.b = __floats2half2_rn(c2, c3);
                g_q[o] = w;
                g_e[o] = __float2half(c4);
            }
            slot = (slot + 1 == WIN) ? 0 : slot + 1;
        }
    }
}

// ---------------------------------------------------------------------------
// Pass C: x box filter with a 21-slot smem ring (per-thread-private columns,
// no barriers). Each voxel read from gmem exactly once; subtract from ring.
// cc per voxel, deterministic block reduction. Thread == z.
// ---------------------------------------------------------------------------
__global__ __launch_bounds__(SZ) void passC() {
    __shared__ H4 rQ[WIN][SZ];
    __shared__ __half rE[WIN][SZ];

    int bid = blockIdx.x;
    const int seg = bid % XSEG;
    int t = bid / XSEG;
    const int y = t % SY;
    const int b = t / SY;
    const int z = threadIdx.x;

    const int x0 = seg * XLEN;
    const size_t strideX = (size_t)SY * SZ;
    const size_t base = ((size_t)b * SX) * strideX + (size_t)y * SZ + z;

    float s0 = 0.f, s1 = 0.f, s2 = 0.f, s3 = 0.f, s4 = 0.f;
    // warmup: fill ring with window [x0-10, x0+10], zeros outside the volume
#pragma unroll
    for (int k = 0; k < WIN; k++) {
        const int xx = x0 - HALF + k;
        H4 h; h.a = __floats2half2_rn(0.f, 0.f); h.b = h.a;
        __half e = __float2half(0.f);
        if (xx >= 0 && xx < SX) {
            size_t o = base + (size_t)xx * strideX;
            h = g_q[o];
            e = g_e[o];
        }
        rQ[k][z] = h;
        rE[k][z] = e;
        float2 a = __half22float2(h.a);
        float2 c = __half22float2(h.b);
        s0 += a.x; s1 += a.y; s2 += c.x; s3 += c.y;
        s4 += __half2float(e);
    }

    const float inv_n = 1.0f / (float)(WIN * WIN * WIN);
    float acc = 0.f;
    int slot = 0;  // oldest = x0-10
    for (int x = x0; x < x0 + XLEN; ++x) {
        float cross = s4 - s0 * s1 * inv_n;
        float Ivar  = s2 - s0 * s0 * inv_n;
        float Jvar  = s3 - s1 * s1 * inv_n;
        acc += (cross * cross) / (Ivar * Jvar + 1e-5f);

        // slide window: remove x-10 (ring), insert x+11 (gmem, once)
        {
            H4 o = rQ[slot][z];
            float2 oa = __half22float2(o.a);
            float2 ob = __half22float2(o.b);
            s0 -= oa.x; s1 -= oa.y; s2 -= ob.x; s3 -= ob.y;
            s4 -= __half2float(rE[slot][z]);
        }
        const int xa = x + HALF + 1;
        H4 h; h.a = __floats2half2_rn(0.f, 0.f); h.b = h.a;
        __half e = __float2half(0.f);
        if (xa < SX) {
            size_t o = base + (size_t)xa * strideX;
            h = g_q[o];
            e = g_e[o];
        }
        rQ[slot][z] = h;
        rE[slot][z] = e;
        float2 a = __half22float2(h.a);
        float2 c = __half22float2(h.b);
        s0 += a.x; s1 += a.y; s2 += c.x; s3 += c.y;
        s4 += __half2float(e);

        slot = (slot + 1 == WIN) ? 0 : slot + 1;
    }

    // deterministic block reduction (160 threads = 5 warps)
    __shared__ float wsum[SZ / 32];
    float v = acc;
#pragma unroll
    for (int off = 16; off; off >>= 1)
        v += __shfl_down_sync(0xffffffffu, v, off);
    if ((threadIdx.x & 31) == 0) wsum[threadIdx.x >> 5] = v;
    __syncthreads();
    if (threadIdx.x == 0) {
        double tot = 0.0;
#pragma unroll
        for (int w = 0; w < SZ / 32; w++) tot += (double)wsum[w];
        g_part[bid] = tot;
    }
}

// ---------------------------------------------------------------------------
// Final: reduce partials, out = 1 - mean(cc)
// ---------------------------------------------------------------------------
__global__ void finalK(float* __restrict__ out) {
    __shared__ double sh[256];
    double v = 0.0;
    for (int i = threadIdx.x; i < NPART; i += 256)
        v += g_part[i];
    sh[threadIdx.x] = v;
    __syncthreads();
    for (int s = 128; s; s >>= 1) {
        if (threadIdx.x < s) sh[threadIdx.x] += sh[threadIdx.x + s];
        __syncthreads();
    }
    if (threadIdx.x == 0)
        out[0] = (float)(1.0 - sh[0] / (double)NF);
}

extern "C" void kernel_launch(void* const* d_in, const int* in_sizes, int n_in,
                              void* d_out, int out_size) {
    const float* I = (const float*)d_in[0];
    const float* J = (const float*)d_in[1];
    float* out = (float*)d_out;

    passAB<<<SB * SX * YSEG, SZ>>>(I, J);
    passC<<<SB * SY * XSEG, SZ>>>();
    finalK<<<1, 256>>>(out);
}

// round 5
// speedup vs baseline: 2.1774x; 1.1850x over previous
#include <cuda_runtime.h>
#include <cuda_fp16.h>

#define SB 2
#define SX 160
#define SY 192
#define SZ 160
#define WIN 21
#define HALF 10
#define NF 9830400ull          // SB*SX*SY*SZ
#define YSEG 2
#define YL (SY / YSEG)         // 96
#define XSEG 2
#define XLEN (SX / XSEG)       // 80
#define NPART (SB * SY * XSEG) // 768
#define LPAD (SZ + 2 * HALF)   // 180
#define S1N (SZ + 18)          // stage1 range [-9, SZ+9), physical offset +9

// Packed fp16: (I,J) in .a, (I2,J2) in .b ; IJ separate half.
struct __align__(8) H4 { __half2 a, b; };

__device__ H4 g_q[NF];
__device__ __half g_e[NF];
__device__ double g_part[NPART];
__device__ int g_count;

// ---------------------------------------------------------------------------
// Fused pass A+B. z-filter = 3-tap stage (packed HADD2) then 7-tap stride-3
// stage; y-filter = per-thread fp32 running sum + 21-line packed fp16 ring
// (ring stores exactly what was added -> subtraction cancels exactly).
// Thread == z; 2 lines per barrier pair.
// ---------------------------------------------------------------------------
__global__ __launch_bounds__(SZ) void passAB(const float* __restrict__ I,
                                             const float* __restrict__ J) {
    __shared__ H4     lQ[2][LPAD];
    __shared__ __half lC[2][LPAD];
    __shared__ H4     s1Q[2][S1N];
    __shared__ __half s1C[2][S1N];
    __shared__ H4     ringQ[WIN][SZ];
    __shared__ __half ringE[WIN][SZ];

    const int z = threadIdx.x;
    int bid = blockIdx.x;
    const int seg = bid % YSEG;
    int t = bid / YSEG;
    const int x = t % SX;
    const int b = t / SX;

    // zero the static z-halo pads once
    if (z < HALF) {
        H4 z4; z4.a = __floats2half2_rn(0.f, 0.f); z4.b = z4.a;
        const __half zh = __float2half(0.f);
#pragma unroll
        for (int l = 0; l < 2; l++) {
            lQ[l][z] = z4; lQ[l][SZ + HALF + z] = z4;
            lC[l][z] = zh; lC[l][SZ + HALF + z] = zh;
        }
    }

    const int y0 = seg * YL;
    const int y1 = y0 + YL;
    const int ystart = (y0 - HALF > 0) ? (y0 - HALF) : 0;  // even
    const size_t planeBase = ((size_t)(b * SX + x)) * SY * SZ;

    float c0 = 0.f, c1 = 0.f, c2 = 0.f, c3 = 0.f, c4 = 0.f;
    int slot = 0;

    __syncthreads();

    for (int y = ystart; y < y1 + HALF; y += 2) {
        // ---- phase 0: stage two lines + products (coalesced along z) ----
#pragma unroll
        for (int l = 0; l < 2; l++) {
            const int yy = y + l;
            float iv = 0.f, jv = 0.f;
            if (yy < SY) {
                size_t o = planeBase + (size_t)yy * SZ + z;
                iv = I[o]; jv = J[o];
            }
            H4 h;
            h.a = __floats2half2_rn(iv, jv);
            h.b = __hmul2(h.a, h.a);
            lQ[l][HALF + z] = h;
            lC[l][HALF + z] = __float2half(iv * jv);
        }
        __syncthreads();

        // ---- phase 1: 3-tap stage over physical [0, S1N) ----
#pragma unroll
        for (int l = 0; l < 2; l++) {
            {
                const int i = z;
                H4 r;
                r.a = __hadd2(__hadd2(lQ[l][i].a, lQ[l][i + 1].a), lQ[l][i + 2].a);
                r.b = __hadd2(__hadd2(lQ[l][i].b, lQ[l][i + 1].b), lQ[l][i + 2].b);
                s1Q[l][i] = r;
                s1C[l][i] = __hadd(__hadd(lC[l][i], lC[l][i + 1]), lC[l][i + 2]);
            }
            if (z < S1N - SZ) {
                const int i = SZ + z;
                H4 r;
                r.a = __hadd2(__hadd2(lQ[l][i].a, lQ[l][i + 1].a), lQ[l][i + 2].a);
                r.b = __hadd2(__hadd2(lQ[l][i].b, lQ[l][i + 1].b), lQ[l][i + 2].b);
                s1Q[l][i] = r;
                s1C[l][i] = __hadd(__hadd(lC[l][i], lC[l][i + 1]), lC[l][i + 2]);
            }
        }
        __syncthreads();

        // ---- phase 2: 7-tap stride-3 stage + y running sum + output ----
#pragma unroll
        for (int l = 0; l < 2; l++) {
            const int ycur = y + l;
            H4 hsum = s1Q[l][z];
            __half e = s1C[l][z];
#pragma unroll
            for (int j = 3; j <= 18; j += 3) {
                H4 v = s1Q[l][z + j];
                hsum.a = __hadd2(hsum.a, v.a);
                hsum.b = __hadd2(hsum.b, v.b);
                e = __hadd(e, s1C[l][z + j]);
            }

            if (ycur - WIN >= ystart) {
                H4 o = ringQ[slot][z];
                float2 oa = __half22float2(o.a);
                float2 ob = __half22float2(o.b);
                c0 -= oa.x; c1 -= oa.y; c2 -= ob.x; c3 -= ob.y;
                c4 -= __half2float(ringE[slot][z]);
            }
            ringQ[slot][z] = hsum;
            ringE[slot][z] = e;
            float2 ra = __half22float2(hsum.a);
            float2 rb = __half22float2(hsum.b);
            c0 += ra.x; c1 += ra.y; c2 += rb.x; c3 += rb.y;
            c4 += __half2float(e);

            const int yo = ycur - HALF;
            if (yo >= y0) {
                size_t o = planeBase + (size_t)yo * SZ + z;
                H4 w;
                w.a = __floats2half2_rn(c0, c1);
                w.b = __floats2half2_rn(c2, c3);
                g_q[o] = w;
                g_e[o] = __float2half(c4);
            }
            slot = (slot + 1 == WIN) ? 0 : slot + 1;
        }
    }
}

// ---------------------------------------------------------------------------
// Pass C: x box filter with 5 running sums; subtract re-reads gmem (L1 hit),
// adds are batch-prefetched (unroll 4, MLP 8). cc per voxel; deterministic
// block partial; the last block does a fixed-order final reduction.
// ---------------------------------------------------------------------------
__global__ __launch_bounds__(SZ) void passC(float* __restrict__ out) {
    int bid = blockIdx.x;
    const int seg = bid % XSEG;
    int t = bid / XSEG;
    const int y = t % SY;
    const int b = t / SY;
    const int z = threadIdx.x;

    const int x0 = seg * XLEN;
    const size_t strideX = (size_t)SY * SZ;
    const size_t base = ((size_t)b * SX) * strideX + (size_t)y * SZ + z;

    float s0 = 0.f, s1 = 0.f, s2 = 0.f, s3 = 0.f, s4 = 0.f;
    // warmup: window [x0-10, x0+10], zeros outside (independent loads)
#pragma unroll
    for (int k = 0; k < WIN; k++) {
        const int xx = x0 - HALF + k;
        if (xx >= 0 && xx < SX) {
            size_t o = base + (size_t)xx * strideX;
            H4 h = g_q[o];
            __half e = g_e[o];
            float2 a = __half22float2(h.a);
            float2 c = __half22float2(h.b);
            s0 += a.x; s1 += a.y; s2 += c.x; s3 += c.y;
            s4 += __half2float(e);
        }
    }

    const float inv_n = 1.0f / (float)(WIN * WIN * WIN);
    float acc = 0.f;

    for (int xb = 0; xb < XLEN; xb += 4) {
        H4 ha[4], hr[4];
        __half ea[4], er[4];
        // batched loads: 8 independent (MLP), front of the unrolled body
#pragma unroll
        for (int j = 0; j < 4; j++) {
            const int xa = x0 + xb + j + HALF + 1;
            ha[j].a = __floats2half2_rn(0.f, 0.f); ha[j].b = ha[j].a;
            ea[j] = __float2half(0.f);
            if (xa < SX) {
                size_t o = base + (size_t)xa * strideX;
                ha[j] = g_q[o]; ea[j] = g_e[o];
            }
        }
#pragma unroll
        for (int j = 0; j < 4; j++) {
            const int xr = x0 + xb + j - HALF;
            hr[j].a = __floats2half2_rn(0.f, 0.f); hr[j].b = hr[j].a;
            er[j] = __float2half(0.f);
            if (xr >= 0) {
                size_t o = base + (size_t)xr * strideX;
                hr[j] = g_q[o]; er[j] = g_e[o];   // read 21 steps ago -> L1
            }
        }
#pragma unroll
        for (int j = 0; j < 4; j++) {
            float cross = s4 - s0 * s1 * inv_n;
            float Ivar  = s2 - s0 * s0 * inv_n;
            float Jvar  = s3 - s1 * s1 * inv_n;
            acc += (cross * cross) / (Ivar * Jvar + 1e-5f);

            float2 aa = __half22float2(ha[j].a);
            float2 ab = __half22float2(ha[j].b);
            float2 ra = __half22float2(hr[j].a);
            float2 rb = __half22float2(hr[j].b);
            s0 += aa.x - ra.x; s1 += aa.y - ra.y;
            s2 += ab.x - rb.x; s3 += ab.y - rb.y;
            s4 += __half2float(ea[j]) - __half2float(er[j]);
        }
    }

    // deterministic block reduction (160 threads = 5 warps)
    __shared__ float wsum[SZ / 32];
    __shared__ int isLast;
    float v = acc;
#pragma unroll
    for (int off = 16; off; off >>= 1)
        v += __shfl_down_sync(0xffffffffu, v, off);
    if ((threadIdx.x & 31) == 0) wsum[threadIdx.x >> 5] = v;
    __syncthreads();
    if (threadIdx.x == 0) {
        double tot = 0.0;
#pragma unroll
        for (int w = 0; w < SZ / 32; w++) tot += (double)wsum[w];
        g_part[bid] = tot;
        __threadfence();
        int n = atomicAdd(&g_count, 1);
        isLast = (n == NPART - 1);
    }
    __syncthreads();

    // last block: fixed-order final reduction (deterministic)
    if (isLast) {
        __shared__ double sh[256];
        double cv = 0.0;
        const int chunk = 5;                 // 160 * 5 = 800 >= 768
        int lo = threadIdx.x * chunk;
        for (int i = lo; i < lo + chunk && i < NPART; ++i)
            cv += g_part[i];
        sh[threadIdx.x] = cv;
        if (threadIdx.x < 256 - SZ) sh[SZ + threadIdx.x] = 0.0;
        __syncthreads();
        for (int s = 128; s; s >>= 1) {
            if (threadIdx.x < s) sh[threadIdx.x] += sh[threadIdx.x + s];
            __syncthreads();
        }
        if (threadIdx.x == 0) {
            out[0] = (float)(1.0 - sh[0] / (double)NF);
            g_count = 0;                      // reset for next graph replay
        }
    }
}

extern "C" void kernel_launch(void* const* d_in, const int* in_sizes, int n_in,
                              void* d_out, int out_size) {
    const float* I = (const float*)d_in[0];
    const float* J = (const float*)d_in[1];
    float* out = (float*)d_out;

    passAB<<<SB * SX * YSEG, SZ>>>(I, J);
    passC<<<NPART, SZ>>>(out);
}